// round 11
// baseline (speedup 1.0000x reference)
#include <cuda_runtime.h>
#include <cstdint>

#define T_DIM 4096
#define K_DIM 16384
#define HCN 4
#define N_OUT 24
#define NP 12          // float2 pairs across N
#define MB 64          // rows per CTA (8 warps x RT)
#define KSPLIT 8
#define KCHUNK (K_DIM / KSPLIT)   // 2048
#define KT 512         // weight K tile staged in smem
#define NTILES (KCHUNK / KT)      // 4
#define RT 8           // rows per warp
#define NTHREADS 256
#define PSTRIDE 524    // u64 stride per pair in smem (524%16=12 -> conflict-free)
#define PPAD 13        // padded pair stride for reduction

#define STAGE_K 64                 // k per x pipeline stage
#define NSTG (KCHUNK / STAGE_K)    // 32 stages per chunk
#define NSLOTS 3                   // x smem slots (2 in flight)
#define XSLOT_BYTES (MB * STAGE_K * 4)        // 16384
#define WBYTES (NP * PSTRIDE * 8)             // 50304
#define SMEM_BYTES (WBYTES + NSLOTS * XSLOT_BYTES)  // 99456 (2 CTAs/SM fit)

// Scratch (device globals). Transposed [split][pair][row] for coalesced reads.
__device__ float2 g_hpart[KSPLIT][NP][T_DIM];
__device__ float  g_sspart[KSPLIT][T_DIM];

using u64 = unsigned long long;

__device__ __forceinline__ u64 fma2(u64 a, u64 b, u64 c) {
    u64 d;
    asm("fma.rn.f32x2 %0, %1, %2, %3;" : "=l"(d) : "l"(a), "l"(b), "l"(c));
    return d;
}
__device__ __forceinline__ u64 pack2(float x) {
    u64 d;
    asm("mov.b64 %0, {%1, %1};" : "=l"(d) : "f"(x));
    return d;
}
__device__ __forceinline__ float2 u2f(u64 a) {
    float2 f;
    asm("mov.b64 {%0, %1}, %2;" : "=f"(f.x), "=f"(f.y) : "l"(a));
    return f;
}
__device__ __forceinline__ float frcp(float a) {
    float r;
    asm("rcp.approx.f32 %0, %1;" : "=f"(r) : "f"(a));
    return r;
}
__device__ __forceinline__ float f4get(const float4& v, int s) {
    return s == 0 ? v.x : (s == 1 ? v.y : (s == 2 ? v.z : v.w));
}
__device__ __forceinline__ void cp_async16(uint32_t dst_smem, const void* src) {
    asm volatile("cp.async.cg.shared.global [%0], [%1], 16;"
                 :: "r"(dst_smem), "l"(src));
}
__device__ __forceinline__ void cp_commit() {
    asm volatile("cp.async.commit_group;");
}
template <int N>
__device__ __forceinline__ void cp_wait() {
    asm volatile("cp.async.wait_group %0;" :: "n"(N));
}

// ---------------------------------------------------------------------------
// Kernel A — quarter-split + cp.async pipeline + 2 CTAs/SM + rotated rows.
// Warp: lane = g*8 + l7; group g owns output pairs [3g,3g+3); l7 = k lane.
// Row rotation: thread (g,l7) accumulator j corresponds to warp row
// (j + 2g) & 7. Hence local rows 0,1 are globally rows 2g, 2g+1 — each group
// computes ss for exactly its 2 rows (2 fmaf/s-step instead of 8, statically
// indexed). x LDS.128 stays conflict-free: each 8-lane phase group reads one
// row's contiguous 128B regardless of rotation.
// ---------------------------------------------------------------------------
extern "C" __global__ void __launch_bounds__(NTHREADS, 2)
mhc_gemm_kernel(const float* __restrict__ x, const float* __restrict__ w) {
    extern __shared__ char smem[];
    u64* sw = (u64*)smem;  // weights: [12 pairs][PSTRIDE u64]
    const uint32_t smem_u32 = (uint32_t)__cvta_generic_to_shared(smem);
    const uint32_t xbase = smem_u32 + WBYTES;

    const int tid = threadIdx.x;
    const int wid = tid >> 5;          // warp 0..7
    const int g   = (tid >> 3) & 3;    // pair group 0..3
    const int l7  = tid & 7;           // k lane 0..7
    const int p3  = g * 3;
    const int bm = blockIdx.x;
    const int bk = blockIdx.y;
    const int row0 = bm * MB;

    // x fill mapping: thread t copies 4x16B for row = t>>2, quarter q = t&3
    const int frow = tid >> 2, fq = tid & 3;
    const float* fsrc_base =
        x + (size_t)(row0 + frow) * K_DIM + bk * KCHUNK + fq * 16;
    const uint32_t fdst_base = xbase + (uint32_t)(frow * (STAGE_K * 4) + fq * 64);

    // Per-thread rotated row byte offsets within an x slot (row stride 256B)
    uint32_t rowoff[RT];
#pragma unroll
    for (int r = 0; r < RT; r++)
        rowoff[r] = (uint32_t)((wid * RT + ((r + 2 * g) & 7)) * (STAGE_K * 4));

    u64 acc[RT][3];
    float ssa = 0.f, ssb = 0.f;   // ss for warp rows 2g, 2g+1 (local 0,1)
#pragma unroll
    for (int r = 0; r < RT; r++)
#pragma unroll
        for (int j = 0; j < 3; j++) acc[r][j] = 0ull;

    // Prologue: fill stages 0,1
#pragma unroll
    for (int st = 0; st < NSLOTS - 1; st++) {
        const float* src = fsrc_base + st * STAGE_K;
        uint32_t dst = fdst_base + st * XSLOT_BYTES;
#pragma unroll
        for (int i = 0; i < 4; i++)
            cp_async16(dst + i * 16, src + i * 4);
        cp_commit();
    }

    int slot = 0;   // st % NSLOTS, tracked incrementally
    for (int tile = 0; tile < NTILES; tile++) {
        const int k0 = bk * KCHUNK + tile * KT;

        __syncthreads();   // prev tile's compute done before restaging weights
        // Stage W[k0..k0+KT)[0:24) -> sw[p][(k&3)*128 + (k>>2)]
#pragma unroll
        for (int it = 0; it < (KT * 6) / NTHREADS; it++) {
            int idx = tid + NTHREADS * it;
            int kk = idx / 6, q = idx % 6;
            float4 v = *(const float4*)(w + (size_t)(k0 + kk) * N_OUT + q * 4);
            int base = (kk & 3) * 128 + (kk >> 2);
            ((float2*)sw)[(2 * q + 0) * PSTRIDE + base] = make_float2(v.x, v.y);
            ((float2*)sw)[(2 * q + 1) * PSTRIDE + base] = make_float2(v.z, v.w);
        }

        for (int j = 0; j < KT / STAGE_K; j++) {   // 8 x-stages per weight tile
            const int st = tile * (KT / STAGE_K) + j;

            cp_wait<1>();        // stage st landed (st+1 may be in flight)
            __syncthreads();     // data visible; prev-iter consumers done

            const char* xs = smem + WBYTES + slot * XSLOT_BYTES;
#pragma unroll
            for (int bi = 0; bi < 2; bi++) {
                float4 xv[RT];
#pragma unroll
                for (int r = 0; r < RT; r++)
                    xv[r] = *(const float4*)(xs + rowoff[r] + ((bi * 8 + l7) << 4));
                const int kf4 = j * 16 + bi * 8 + l7;  // within weight tile
#pragma unroll
                for (int s = 0; s < 4; s++) {
                    u64 wp[3];
#pragma unroll
                    for (int jj = 0; jj < 3; jj++)
                        wp[jj] = sw[(p3 + jj) * PSTRIDE + s * 128 + kf4];
#pragma unroll
                    for (int r = 0; r < RT; r++) {
                        float xsv = f4get(xv[r], s);
                        u64 X = pack2(xsv);
#pragma unroll
                        for (int jj = 0; jj < 3; jj++)
                            acc[r][jj] = fma2(X, wp[jj], acc[r][jj]);
                    }
                    // ss only for this group's two rows (local 0,1)
                    float xa = f4get(xv[0], s), xb = f4get(xv[1], s);
                    ssa = fmaf(xa, xa, ssa);
                    ssb = fmaf(xb, xb, ssb);
                }
            }

            // Refill stage st+2 into slot (st+2)%3 (consumed at iter st-1)
            if (st + NSLOTS - 1 < NSTG) {
                const float* src = fsrc_base + (st + NSLOTS - 1) * STAGE_K;
                int rslot = slot + 2;
                if (rslot >= NSLOTS) rslot -= NSLOTS;
                uint32_t dst = fdst_base + rslot * XSLOT_BYTES;
#pragma unroll
                for (int i = 0; i < 4; i++)
                    cp_async16(dst + i * 16, src + i * 4);
            }
            cp_commit();   // keep group count aligned with stage index
            if (++slot == NSLOTS) slot = 0;
        }
    }

    cp_wait<0>();
    __syncthreads();

    // Cross-k-lane reduction via smem (overlays weight buffer + x slots).
    float2* red = (float2*)smem;                                 // [64][8][PPAD]
    float* ssred = (float*)(smem + (size_t)MB * 8 * PPAD * 8);   // [64][8]
#pragma unroll
    for (int r = 0; r < RT; r++) {
        int rl = wid * RT + ((r + 2 * g) & 7);   // rotated row
#pragma unroll
        for (int jj = 0; jj < 3; jj++)
            red[((size_t)rl * 8 + l7) * PPAD + p3 + jj] = u2f(acc[r][jj]);
    }
    {
        int rl0 = wid * RT + 2 * g;
        ssred[(rl0 + 0) * 8 + l7] = ssa;
        ssred[(rl0 + 1) * 8 + l7] = ssb;
    }
    __syncthreads();

    // 64 rows x 12 pairs = 768 columns; 3 per thread
#pragma unroll
    for (int jj = 0; jj < 3; jj++) {
        int col = jj * NTHREADS + tid;
        int p = col >> 6, rl = col & 63;  // lanes consecutive in rl -> coalesced
        float sx = 0.f, sy = 0.f;
#pragma unroll
        for (int t = 0; t < 8; t++) {
            float2 a = red[((size_t)rl * 8 + t) * PPAD + p];
            sx += a.x;
            sy += a.y;
        }
        g_hpart[bk][p][row0 + rl] = make_float2(sx, sy);
    }
    if (tid < MB) {
        float s = 0.f;
#pragma unroll
        for (int t = 0; t < 8; t++) s += ssred[tid * 8 + t];
        g_sspart[bk][row0 + tid] = s;
    }
}

// ---------------------------------------------------------------------------
// Kernel B (known-good R4 form): 1 row/thread, grid 128 x 32.
// rcp.approx only; convergence checked every 8 iterations via
// multiply-compare. Cap 400 = reference MAX_IT^2.
// ---------------------------------------------------------------------------
extern "C" __global__ void __launch_bounds__(32)
mhc_finish_kernel(const float* __restrict__ bias, const float* __restrict__ alpha,
                  float* __restrict__ out) {
    int row = blockIdx.x * 32 + threadIdx.x;

    float h[N_OUT];
#pragma unroll
    for (int p = 0; p < NP; p++) {
        float sx = 0.f, sy = 0.f;
#pragma unroll
        for (int c = 0; c < KSPLIT; c++) {
            float2 a = g_hpart[c][p][row];
            sx += a.x;
            sy += a.y;
        }
        h[2 * p] = sx;
        h[2 * p + 1] = sy;
    }
    float ss = 0.f;
#pragma unroll
    for (int c = 0; c < KSPLIT; c++) ss += g_sspart[c][row];

    float r_inv = rsqrtf(ss * (1.0f / K_DIM));
    float a0 = alpha[0], a1 = alpha[1], a2 = alpha[2];

    float pre[HCN], post[HCN], H[HCN][HCN];
#pragma unroll
    for (int n = 0; n < HCN; n++) {
        float z0 = fmaf(r_inv * a0, h[n], bias[n]);
        pre[n] = 1.f / (1.f + __expf(-z0));
        float z1 = fmaf(r_inv * a1, h[HCN + n], bias[HCN + n]);
        post[n] = 2.f / (1.f + __expf(-z1));
    }
#pragma unroll
    for (int i = 0; i < HCN; i++)
#pragma unroll
        for (int j = 0; j < HCN; j++) {
            float z = fmaf(r_inv * a2, h[8 + 4 * i + j], bias[8 + 4 * i + j]);
            H[i][j] = __expf(z);
        }

    const float EPSV = 1e-12f;
    float u[4] = {1.f, 1.f, 1.f, 1.f}, v[4] = {1.f, 1.f, 1.f, 1.f};
    for (int o = 0; o < 50; o++) {          // 50 blocks x 8 iters = 400 max
        float vp0 = v[0], vp1 = v[1], vp2 = v[2], vp3 = v[3];
#pragma unroll
        for (int s = 0; s < 8; s++) {
            float nu[4];
#pragma unroll
            for (int i = 0; i < 4; i++) {
                float uv = fmaf(H[i][3], v[3],
                           fmaf(H[i][2], v[2],
                           fmaf(H[i][1], v[1],
                           fmaf(H[i][0], v[0], EPSV))));
                nu[i] = frcp(uv);
            }
#pragma unroll
            for (int j = 0; j < 4; j++) {
                float vu = fmaf(H[3][j], nu[3],
                           fmaf(H[2][j], nu[2],
                           fmaf(H[1][j], nu[1],
                           fmaf(H[0][j], nu[0], EPSV))));
                v[j] = frcp(vu);
            }
            u[0] = nu[0]; u[1] = nu[1]; u[2] = nu[2]; u[3] = nu[3];
        }
        float m = fabsf(v[0] - vp0) - 1e-6f * fabsf(v[0]);
        m = fmaxf(m, fabsf(v[1] - vp1) - 1e-6f * fabsf(v[1]));
        m = fmaxf(m, fabsf(v[2] - vp2) - 1e-6f * fabsf(v[2]));
        m = fmaxf(m, fabsf(v[3] - vp3) - 1e-6f * fabsf(v[3]));
        if (m <= 0.f) break;
    }

    ((float4*)out)[row] = make_float4(pre[0], pre[1], pre[2], pre[3]);
    ((float4*)(out + (size_t)T_DIM * HCN))[row] =
        make_float4(post[0], post[1], post[2], post[3]);
    float4* res = (float4*)(out + 2 * (size_t)T_DIM * HCN + (size_t)row * 16);
#pragma unroll
    for (int i = 0; i < 4; i++) {
        res[i] = make_float4(u[i] * H[i][0] * v[0], u[i] * H[i][1] * v[1],
                             u[i] * H[i][2] * v[2], u[i] * H[i][3] * v[3]);
    }
}

// ---------------------------------------------------------------------------
extern "C" void kernel_launch(void* const* d_in, const int* in_sizes, int n_in,
                              void* d_out, int out_size) {
    const float* x = (const float*)d_in[0];
    const float* w = (const float*)d_in[1];
    const float* bias = (const float*)d_in[2];
    const float* alpha = (const float*)d_in[3];
    float* out = (float*)d_out;

    cudaFuncSetAttribute(mhc_gemm_kernel,
                         cudaFuncAttributeMaxDynamicSharedMemorySize,
                         SMEM_BYTES);

    dim3 grid(T_DIM / MB, KSPLIT);
    mhc_gemm_kernel<<<grid, NTHREADS, SMEM_BYTES>>>(x, w);
    mhc_finish_kernel<<<T_DIM / 32, 32>>>(bias, alpha, out);
}

// round 14
// speedup vs baseline: 1.3681x; 1.3681x over previous
#include <cuda_runtime.h>
#include <cuda_bf16.h>
#include <cstdint>

#define T_DIM 4096
#define K_DIM 16384
#define HCN 4
#define N_OUT 24
#define KSPLIT 8
#define KCHUNK 2048
#define NKS 128          // k16 steps per chunk
#define NTHREADS 256

// Device globals (no allocation allowed)
__device__ float g_hpart[KSPLIT][T_DIM][32];   // 24 used, padded to 32
__device__ float g_sspart[KSPLIT][T_DIM];
__device__ uint4 g_wfrag[1024 * 32 * 3];       // per-lane B fragments, 1.5MB

// ---------------- helpers ----------------
__device__ __forceinline__ uint32_t pack_hi(float v0, float v1, float& l0, float& l1) {
    uint32_t h0 = __float_as_uint(v0) & 0xffff0000u;
    uint32_t h1 = __float_as_uint(v1) & 0xffff0000u;
    l0 = v0 - __uint_as_float(h0);
    l1 = v1 - __uint_as_float(h1);
    return (h0 >> 16) | h1;   // lower 16 = v0(hi), upper 16 = v1(hi)
}
__device__ __forceinline__ uint32_t pack_bf2(float lo_elem, float hi_elem) {
    // returns {upper=hi_elem, lower=lo_elem} as bf16x2
    uint32_t d;
    asm("cvt.rn.bf16x2.f32 %0, %1, %2;" : "=r"(d) : "f"(hi_elem), "f"(lo_elem));
    return d;
}
__device__ __forceinline__ float frcp(float a) {
    float r;
    asm("rcp.approx.f32 %0, %1;" : "=f"(r) : "f"(a));
    return r;
}
#define MMA(d, a0, a1, a2, a3, b0, b1)                                        \
    asm volatile("mma.sync.aligned.m16n8k16.row.col.f32.bf16.bf16.f32 "       \
                 "{%0,%1,%2,%3}, {%4,%5,%6,%7}, {%8,%9}, {%0,%1,%2,%3};"      \
                 : "+f"(d[0]), "+f"(d[1]), "+f"(d[2]), "+f"(d[3])             \
                 : "r"(a0), "r"(a1), "r"(a2), "r"(a3), "r"(b0), "r"(b1))

// ---------------------------------------------------------------------------
// Kernel W: precompute B fragments (hi/lo bf16) in mma.sync per-lane order.
// Tile t = k16 step (0..1023). For lane l, ntile nt: col = nt*8 + (l>>2),
// k0 = (l&3)*2. b0 = {B[k0][col], B[k0+1][col]}, b1 = {B[k0+8], B[k0+9]}.
// uint4 = (bhi0, bhi1, blo0, blo1).
// ---------------------------------------------------------------------------
extern "C" __global__ void __launch_bounds__(32)
mhc_wconv_kernel(const float* __restrict__ w) {
    const int t = blockIdx.x;
    const int lane = threadIdx.x;
    const int k0 = (lane & 3) * 2;
    const int rowq = lane >> 2;
#pragma unroll
    for (int nt = 0; nt < 3; nt++) {
        int col = nt * 8 + rowq;
        const float* wb = w + (size_t)(t * 16) * N_OUT + col;
        float v00 = wb[(k0 + 0) * N_OUT], v01 = wb[(k0 + 1) * N_OUT];
        float v08 = wb[(k0 + 8) * N_OUT], v09 = wb[(k0 + 9) * N_OUT];
        float l00, l01, l08, l09;
        uint32_t bhi0 = pack_hi(v00, v01, l00, l01);
        uint32_t bhi1 = pack_hi(v08, v09, l08, l09);
        uint32_t blo0 = pack_bf2(l00, l01);
        uint32_t blo1 = pack_bf2(l08, l09);
        g_wfrag[(t * 32 + lane) * 3 + nt] = make_uint4(bhi0, bhi1, blo0, blo1);
    }
}

// ---------------------------------------------------------------------------
// Kernel A: mma.sync bf16 3-split GEMM. Grid (32, 8): CTA = 128 rows x one
// 2048-k chunk; warp w owns rows [bm*128 + w*16, +16). Per k16 step each
// thread loads its A-fragment floats straight from x (4x LDG.64), converts
// to hi/lo bf16 fragments, loads 3 preswizzled B-fragment uint4, issues
// 9 HMMA (3 ntiles x 3 split terms) into 12 fp32 accumulators. ss computed
// exactly in fp32 from the same loads. No smem, no barriers.
// ---------------------------------------------------------------------------
extern "C" __global__ void __launch_bounds__(NTHREADS)
mhc_gemm_kernel(const float* __restrict__ x) {
    const int tid = threadIdx.x;
    const int wid = tid >> 5;
    const int lane = tid & 31;
    const int bm = blockIdx.x;
    const int bk = blockIdx.y;

    const int r0 = bm * 128 + wid * 16 + (lane >> 2);   // fragment row (group)
    const int r1 = r0 + 8;
    const int k0 = (lane & 3) * 2;
    const float* px0 = x + (size_t)r0 * K_DIM + bk * KCHUNK + k0;
    const float* px1 = x + (size_t)r1 * K_DIM + bk * KCHUNK + k0;
    const uint4* bfr = g_wfrag + ((size_t)(bk * NKS) * 32 + lane) * 3;

    float acc[3][4];
#pragma unroll
    for (int nt = 0; nt < 3; nt++)
#pragma unroll
        for (int j = 0; j < 4; j++) acc[nt][j] = 0.f;
    float ss0 = 0.f, ss1 = 0.f;

#pragma unroll 4
    for (int ks = 0; ks < NKS; ks++) {
        float2 x00 = __ldcs((const float2*)(px0 + ks * 16));
        float2 x01 = __ldcs((const float2*)(px0 + ks * 16 + 8));
        float2 x10 = __ldcs((const float2*)(px1 + ks * 16));
        float2 x11 = __ldcs((const float2*)(px1 + ks * 16 + 8));
        uint4 b0 = bfr[ks * 96 + 0];   // ntile 0: {bhi0,bhi1,blo0,blo1}
        uint4 b1 = bfr[ks * 96 + 1];
        uint4 b2 = bfr[ks * 96 + 2];

        // A fragments: a0=(r0,k0/k0+1) a1=(r1,..) a2=(r0,k0+8/+9) a3=(r1,..)
        float l00, l01, l02, l03, l10, l11, l12, l13;
        uint32_t ah0 = pack_hi(x00.x, x00.y, l00, l01);
        uint32_t ah1 = pack_hi(x10.x, x10.y, l10, l11);
        uint32_t ah2 = pack_hi(x01.x, x01.y, l02, l03);
        uint32_t ah3 = pack_hi(x11.x, x11.y, l12, l13);
        uint32_t al0 = pack_bf2(l00, l01);
        uint32_t al1 = pack_bf2(l10, l11);
        uint32_t al2 = pack_bf2(l02, l03);
        uint32_t al3 = pack_bf2(l12, l13);

        ss0 = fmaf(x00.x, x00.x, fmaf(x00.y, x00.y,
              fmaf(x01.x, x01.x, fmaf(x01.y, x01.y, ss0))));
        ss1 = fmaf(x10.x, x10.x, fmaf(x10.y, x10.y,
              fmaf(x11.x, x11.x, fmaf(x11.y, x11.y, ss1))));

        // 3 split terms per ntile: Ahi*Bhi + Ahi*Blo + Alo*Bhi
        MMA(acc[0], ah0, ah1, ah2, ah3, b0.x, b0.y);
        MMA(acc[0], ah0, ah1, ah2, ah3, b0.z, b0.w);
        MMA(acc[0], al0, al1, al2, al3, b0.x, b0.y);
        MMA(acc[1], ah0, ah1, ah2, ah3, b1.x, b1.y);
        MMA(acc[1], ah0, ah1, ah2, ah3, b1.z, b1.w);
        MMA(acc[1], al0, al1, al2, al3, b1.x, b1.y);
        MMA(acc[2], ah0, ah1, ah2, ah3, b2.x, b2.y);
        MMA(acc[2], ah0, ah1, ah2, ah3, b2.z, b2.w);
        MMA(acc[2], al0, al1, al2, al3, b2.x, b2.y);
    }

    // Epilogue: D row=r0 cols (lane&3)*2,+1 are acc[nt][0..1]; row=r1 -> 2..3
#pragma unroll
    for (int nt = 0; nt < 3; nt++) {
        int col = nt * 8 + (lane & 3) * 2;
        *(float2*)&g_hpart[bk][r0][col] = make_float2(acc[nt][0], acc[nt][1]);
        *(float2*)&g_hpart[bk][r1][col] = make_float2(acc[nt][2], acc[nt][3]);
    }
    // ss: reduce over the 4 lanes of the quad (distinct k), write per row
    ss0 += __shfl_xor_sync(0xffffffffu, ss0, 1);
    ss0 += __shfl_xor_sync(0xffffffffu, ss0, 2);
    ss1 += __shfl_xor_sync(0xffffffffu, ss1, 1);
    ss1 += __shfl_xor_sync(0xffffffffu, ss1, 2);
    if ((lane & 3) == 0) {
        g_sspart[bk][r0] = ss0;
        g_sspart[bk][r1] = ss1;
    }
}

// ---------------------------------------------------------------------------
// Kernel B: reduce K-split partials, activations, Sinkhorn (known-good form).
// Cap 400 = reference MAX_IT^2; early-exit every 8 iters via mult-compare.
// ---------------------------------------------------------------------------
extern "C" __global__ void __launch_bounds__(32)
mhc_finish_kernel(const float* __restrict__ bias, const float* __restrict__ alpha,
                  float* __restrict__ out) {
    int row = blockIdx.x * 32 + threadIdx.x;

    float h[N_OUT];
#pragma unroll
    for (int n = 0; n < N_OUT; n++) h[n] = 0.f;
#pragma unroll
    for (int c = 0; c < KSPLIT; c++) {
        const float4* hp = (const float4*)g_hpart[c][row];
#pragma unroll
        for (int q = 0; q < 6; q++) {
            float4 v = hp[q];
            h[q * 4 + 0] += v.x;
            h[q * 4 + 1] += v.y;
            h[q * 4 + 2] += v.z;
            h[q * 4 + 3] += v.w;
        }
    }
    float ss = 0.f;
#pragma unroll
    for (int c = 0; c < KSPLIT; c++) ss += g_sspart[c][row];

    float r_inv = rsqrtf(ss * (1.0f / K_DIM));
    float a0 = alpha[0], a1 = alpha[1], a2 = alpha[2];

    float pre[HCN], post[HCN], H[HCN][HCN];
#pragma unroll
    for (int n = 0; n < HCN; n++) {
        float z0 = fmaf(r_inv * a0, h[n], bias[n]);
        pre[n] = 1.f / (1.f + __expf(-z0));
        float z1 = fmaf(r_inv * a1, h[HCN + n], bias[HCN + n]);
        post[n] = 2.f / (1.f + __expf(-z1));
    }
#pragma unroll
    for (int i = 0; i < HCN; i++)
#pragma unroll
        for (int j = 0; j < HCN; j++) {
            float z = fmaf(r_inv * a2, h[8 + 4 * i + j], bias[8 + 4 * i + j]);
            H[i][j] = __expf(z);
        }

    const float EPSV = 1e-12f;
    float u[4] = {1.f, 1.f, 1.f, 1.f}, v[4] = {1.f, 1.f, 1.f, 1.f};
    for (int o = 0; o < 50; o++) {
        float vp0 = v[0], vp1 = v[1], vp2 = v[2], vp3 = v[3];
#pragma unroll
        for (int s = 0; s < 8; s++) {
            float nu[4];
#pragma unroll
            for (int i = 0; i < 4; i++) {
                float uv = fmaf(H[i][3], v[3], fmaf(H[i][2], v[2],
                           fmaf(H[i][1], v[1], fmaf(H[i][0], v[0], EPSV))));
                nu[i] = frcp(uv);
            }
#pragma unroll
            for (int j = 0; j < 4; j++) {
                float vu = fmaf(H[3][j], nu[3], fmaf(H[2][j], nu[2],
                           fmaf(H[1][j], nu[1], fmaf(H[0][j], nu[0], EPSV))));
                v[j] = frcp(vu);
            }
            u[0] = nu[0]; u[1] = nu[1]; u[2] = nu[2]; u[3] = nu[3];
        }
        float m = fabsf(v[0] - vp0) - 1e-6f * fabsf(v[0]);
        m = fmaxf(m, fabsf(v[1] - vp1) - 1e-6f * fabsf(v[1]));
        m = fmaxf(m, fabsf(v[2] - vp2) - 1e-6f * fabsf(v[2]));
        m = fmaxf(m, fabsf(v[3] - vp3) - 1e-6f * fabsf(v[3]));
        if (m <= 0.f) break;
    }

    ((float4*)out)[row] = make_float4(pre[0], pre[1], pre[2], pre[3]);
    ((float4*)(out + (size_t)T_DIM * HCN))[row] =
        make_float4(post[0], post[1], post[2], post[3]);
    float4* res = (float4*)(out + 2 * (size_t)T_DIM * HCN + (size_t)row * 16);
#pragma unroll
    for (int i = 0; i < 4; i++) {
        res[i] = make_float4(u[i] * H[i][0] * v[0], u[i] * H[i][1] * v[1],
                             u[i] * H[i][2] * v[2], u[i] * H[i][3] * v[3]);
    }
}

// ---------------------------------------------------------------------------
extern "C" void kernel_launch(void* const* d_in, const int* in_sizes, int n_in,
                              void* d_out, int out_size) {
    const float* x = (const float*)d_in[0];
    const float* w = (const float*)d_in[1];
    const float* bias = (const float*)d_in[2];
    const float* alpha = (const float*)d_in[3];
    float* out = (float*)d_out;

    mhc_wconv_kernel<<<1024, 32>>>(w);
    mhc_gemm_kernel<<<dim3(T_DIM / 128, KSPLIT), NTHREADS>>>(x);
    mhc_finish_kernel<<<T_DIM / 32, 32>>>(bias, alpha, out);
}